// round 1
// baseline (speedup 1.0000x reference)
#include <cuda_runtime.h>

// Stacked LSTM wavefront. L=64 layers, T=64 steps, B=16, H=256.
// cell (t,l) needs h(t,l-1) [same diag-1] and c/h(t-1,l) [same diag-1]
// -> process anti-diagonals d = t + l, one kernel launch per diagonal.

#define NL 64
#define NT 64
#define NB 16
#define NH 256
#define KDIM 512   // 2*NH
#define ZDIM 1024  // 4*NH

// Persistent state (device globals; no allocation allowed).
// g_h double-buffered by diagonal parity: diag d writes g_h[d&1], reads g_h[(d&1)^1].
__device__ float g_c[NL][NB][NH];
__device__ float g_h[2][NL][NB][NH];

__global__ void init_kernel(const float* __restrict__ init_state) {
    int idx = blockIdx.x * blockDim.x + threadIdx.x;
    const int total = NL * NB * NH;
    if (idx >= total) return;
    int l = idx / (NB * NH);
    int r = idx % (NB * NH);
    float c0 = init_state[l * 2 * NB * NH + r];
    float h0 = init_state[l * 2 * NB * NH + NB * NH + r];
    ((float*)g_c)[idx] = c0;
    ((float*)g_h)[idx] = h0;          // parity 0 copy
    ((float*)g_h)[total + idx] = h0;  // parity 1 copy
}

__device__ __forceinline__ float sigmoidf_(float v) {
    return 1.0f / (1.0f + __expf(-v) * 0.0f + expf(-v)); // accurate expf
}

// One diagonal. Grid: ncells * 4 blocks of 256 threads.
// Block = (cell, chunk): chunk owns 64 h-columns -> 256 z-columns (4 gates).
// Thread owns one z-column: acc over K=512 for all 16 batch rows.
__global__ __launch_bounds__(256)
void diag_kernel(const float* __restrict__ x, const float* __restrict__ W,
                 const float* __restrict__ bias, float* __restrict__ out, int d) {
    __shared__ float a_sh[NB][KDIM];  // A = [inp | h_prev], row-major [b][k]; 32 KB

    const int lmin = (d > (NT - 1)) ? (d - (NT - 1)) : 0;
    const int cell = blockIdx.x >> 2;
    const int chunk = blockIdx.x & 3;
    const int l = lmin + cell;
    const int t = d - l;
    const int tid = threadIdx.x;
    const int parity = d & 1;

    const float* __restrict__ hin = &g_h[parity ^ 1][(l == 0) ? 0 : (l - 1)][0][0];
    const float* __restrict__ lh  = &g_h[parity ^ 1][l][0][0];

    // Stage A into SMEM: a_sh[b][k], k<256 = input, k>=256 = recurrent h.
    // tid -> k (coalesced LDG, conflict-free STS), loop over b.
    #pragma unroll
    for (int m = 0; m < NB; m++) {
        int k = tid;
        float vin = (l == 0) ? x[(m * NT + t) * NH + k] : hin[m * NH + k];
        a_sh[m][k]       = vin;
        a_sh[m][k + 256] = lh[m * NH + k];
    }
    __syncthreads();

    // z-column for this thread
    const int gate = tid >> 6;          // 0..3  (i, j, f, o)
    const int hc   = tid & 63;          // 0..63 within chunk
    const int col  = chunk * 64 + hc;   // h-column 0..255
    const int j    = gate * NH + col;   // z-column 0..1023

    float acc[NB];
    #pragma unroll
    for (int bb = 0; bb < NB; bb++) acc[bb] = 0.0f;

    const float* __restrict__ wp = W + j;  // W[k][j] = W[k*ZDIM + j]

    #pragma unroll 2
    for (int k = 0; k < KDIM; k += 4) {
        float w0 = __ldg(&wp[(size_t)(k + 0) * ZDIM]);
        float w1 = __ldg(&wp[(size_t)(k + 1) * ZDIM]);
        float w2 = __ldg(&wp[(size_t)(k + 2) * ZDIM]);
        float w3 = __ldg(&wp[(size_t)(k + 3) * ZDIM]);
        #pragma unroll
        for (int bb = 0; bb < NB; bb++) {
            float4 a = *(const float4*)&a_sh[bb][k];  // broadcast, conflict-free
            acc[bb] = fmaf(a.x, w0, acc[bb]);
            acc[bb] = fmaf(a.y, w1, acc[bb]);
            acc[bb] = fmaf(a.z, w2, acc[bb]);
            acc[bb] = fmaf(a.w, w3, acc[bb]);
        }
    }

    // Gate exchange through SMEM (alias a_sh; it is dead now).
    __syncthreads();
    float (*z_sh)[64][17] = reinterpret_cast<float (*)[64][17]>(&a_sh[0][0]); // 17.4 KB < 32 KB
    {
        float bj = __ldg(&bias[j]);
        #pragma unroll
        for (int bb = 0; bb < NB; bb++) z_sh[gate][hc][bb] = acc[bb] + bj;
    }
    __syncthreads();

    // Epilogue: tid -> (hc2 = tid&63, bgrp = tid>>6 -> 4 batch rows each)
    const int hc2 = tid & 63;
    const int bg  = tid >> 6;
    const int col2 = chunk * 64 + hc2;

    #pragma unroll
    for (int q = 0; q < 4; q++) {
        int b_ = bg * 4 + q;
        float iv = z_sh[0][hc2][b_];
        float jv = z_sh[1][hc2][b_];
        float fv = z_sh[2][hc2][b_];
        float ov = z_sh[3][hc2][b_];

        float lc = g_c[l][b_][col2];
        float sf = 1.0f / (1.0f + expf(-(fv + 1.0f)));
        float si = 1.0f / (1.0f + expf(-iv));
        float so = 1.0f / (1.0f + expf(-ov));
        float nc = sf * lc + si * tanhf(jv);
        float nh = so * tanhf(nc);

        g_c[l][b_][col2] = nc;
        g_h[parity][l][b_][col2] = nh;
        if (l == NL - 1) {
            out[(b_ * NT + t) * NH + col2] = nh;
        }
    }
}

extern "C" void kernel_launch(void* const* d_in, const int* in_sizes, int n_in,
                              void* d_out, int out_size) {
    const float* x          = (const float*)d_in[0];  // (B,T,H)
    const float* init_state = (const float*)d_in[1];  // (L,2,B,H)
    const float* W          = (const float*)d_in[2];  // (2H,4H)
    const float* bias       = (const float*)d_in[3];  // (4H,)
    float* out              = (float*)d_out;          // (B,T,H)

    {
        int total = NL * NB * NH;
        init_kernel<<<(total + 255) / 256, 256>>>(init_state);
    }

    for (int d = 0; d < NT + NL - 1; d++) {
        int lmin = (d > (NT - 1)) ? (d - (NT - 1)) : 0;
        int lmax = (d < (NL - 1)) ? d : (NL - 1);
        int ncells = lmax - lmin + 1;
        diag_kernel<<<ncells * 4, 256>>>(x, W, bias, out, d);
    }
}